// round 17
// baseline (speedup 1.0000x reference)
#include <cuda_runtime.h>

// Problem constants (B=4, N_obj=8 -> 32 objects, N_v=2048 points, 64 anchors, 16-NN)
#define N_V        2048
#define N_OBJS     32
#define ANCHORS    64
#define KNN        16
#define FPS_THREADS 256
#define PPT        8            // points per thread in FPS (2048/256)
#define FULL       0xffffffffu

// per-anchor pack: (qx, qy, qz, bitcast(anchor_index))
__device__ float4 g_qpack[N_OBJS * ANCHORS];

// ---- packed f32x2 helpers (sm_103a FFMA2 path; per-element IEEE RN).
//      Op sequence bit-verified in R5/R15 (rel_err identical to scalar). ----
__device__ __forceinline__ unsigned long long pk2(float lo, float hi) {
    unsigned long long r; asm("mov.b64 %0,{%1,%2};" : "=l"(r) : "f"(lo), "f"(hi)); return r;
}
__device__ __forceinline__ void upk2(unsigned long long v, float& lo, float& hi) {
    asm("mov.b64 {%0,%1},%2;" : "=f"(lo), "=f"(hi) : "l"(v));
}
__device__ __forceinline__ unsigned long long add2_(unsigned long long a, unsigned long long b) {
    unsigned long long r; asm("add.rn.f32x2 %0,%1,%2;" : "=l"(r) : "l"(a), "l"(b)); return r;
}
__device__ __forceinline__ unsigned long long mul2_(unsigned long long a, unsigned long long b) {
    unsigned long long r; asm("mul.rn.f32x2 %0,%1,%2;" : "=l"(r) : "l"(a), "l"(b)); return r;
}
__device__ __forceinline__ unsigned long long fma2_(unsigned long long a, unsigned long long b,
                                                    unsigned long long c) {
    unsigned long long r; asm("fma.rn.f32x2 %0,%1,%2,%3;" : "=l"(r) : "l"(a), "l"(b), "l"(c)); return r;
}

// ---------------------------------------------------------------------------
// Kernel 1: farthest point sampling — byte-exact the R16 winner:
// f32x2 update pipe, fused local argmax, double-redux warp winner,
// single barrier/iter, light qpack tail.
// ---------------------------------------------------------------------------
__global__ __launch_bounds__(FPS_THREADS) void fps_kernel(const float* __restrict__ pos) {
    const int o = blockIdx.x;
    const float* __restrict__ P = pos + (size_t)o * N_V * 3;

    __shared__ float spts[N_V * 3];                       // 24 KB
    __shared__ unsigned long long swk[2][FPS_THREADS / 32];
    __shared__ int sanch[ANCHORS];

    const int tid  = threadIdx.x;
    const int lane = tid & 31;
    const int wid  = tid >> 5;

    for (int i = tid; i < N_V * 3; i += FPS_THREADS) spts[i] = P[i];
    __syncthreads();

    // own 8 points as 4 packed coordinate pairs
    unsigned long long PX[PPT / 2], PY[PPT / 2], PZ[PPT / 2];
    float md[PPT];
    float bv = -1.0f;
    int   bi = tid;
#pragma unroll
    for (int p = 0; p < PPT / 2; p++) {
        const int j0 = tid + FPS_THREADS * (2 * p);
        const int j1 = tid + FPS_THREADS * (2 * p + 1);
        PX[p] = pk2(spts[j0 * 3 + 0], spts[j1 * 3 + 0]);
        PY[p] = pk2(spts[j0 * 3 + 1], spts[j1 * 3 + 1]);
        PZ[p] = pk2(spts[j0 * 3 + 2], spts[j1 * 3 + 2]);
    }
    // seed distances to point 0 + fused argmax (same scan order as separate)
    {
        const float x0 = spts[0], y0 = spts[1], z0 = spts[2];
        const unsigned long long nqx = pk2(-x0, -x0);
        const unsigned long long nqy = pk2(-y0, -y0);
        const unsigned long long nqz = pk2(-z0, -z0);
#pragma unroll
        for (int p = 0; p < PPT / 2; p++) {
            const unsigned long long dx = add2_(PX[p], nqx);
            const unsigned long long dy = add2_(PY[p], nqy);
            const unsigned long long dz = add2_(PZ[p], nqz);
            unsigned long long s = mul2_(dx, dx);
            s = fma2_(dy, dy, s);
            s = fma2_(dz, dz, s);
            float d0, d1; upk2(s, d0, d1);
            md[2 * p] = d0; md[2 * p + 1] = d1;
            if (d0 > bv) { bv = d0; bi = tid + FPS_THREADS * (2 * p); }
            if (d1 > bv) { bv = d1; bi = tid + FPS_THREADS * (2 * p + 1); }
        }
    }
    if (tid == 0) sanch[0] = 0;

    int buf = 0;
    for (int it = 1; it < ANCHORS; ++it) {
        // warp argmax via double redux (md >= 0 -> float bits monotonic)
        const unsigned u = __float_as_uint(bv);
        const unsigned m = __reduce_max_sync(FULL, u);
        const unsigned ci_inv =
            __reduce_max_sync(FULL, (u == m) ? (unsigned)(0x7FFFFFFF - bi) : 0u);
        if (lane == 0)
            swk[buf][wid] = ((unsigned long long)m << 32) | ci_inv;
        __syncthreads();

        // every thread reduces the 8 warp partials (no second barrier needed)
        unsigned long long best = swk[buf][0];
#pragma unroll
        for (int w = 1; w < FPS_THREADS / 32; w++) {
            const unsigned long long c = swk[buf][w];
            if (c > best) best = c;
        }
        const int bidx = 0x7FFFFFFF - (int)(unsigned)(best & 0xFFFFFFFFull);
        if (tid == 0) sanch[it] = bidx;

        const float qx = spts[bidx * 3 + 0];
        const float qy = spts[bidx * 3 + 1];
        const float qz = spts[bidx * 3 + 2];
        const unsigned long long nqx = pk2(-qx, -qx);
        const unsigned long long nqy = pk2(-qy, -qy);
        const unsigned long long nqz = pk2(-qz, -qz);
        bv = -1.0f; bi = tid;
#pragma unroll
        for (int p = 0; p < PPT / 2; p++) {
            const unsigned long long dx = add2_(PX[p], nqx);
            const unsigned long long dy = add2_(PY[p], nqy);
            const unsigned long long dz = add2_(PZ[p], nqz);
            unsigned long long s = mul2_(dx, dx);
            s = fma2_(dy, dy, s);
            s = fma2_(dz, dz, s);
            float d0, d1; upk2(s, d0, d1);
            const float m0 = fminf(md[2 * p], d0);
            const float m1 = fminf(md[2 * p + 1], d1);
            md[2 * p] = m0; md[2 * p + 1] = m1;
            if (m0 > bv) { bv = m0; bi = tid + FPS_THREADS * (2 * p); }
            if (m1 > bv) { bv = m1; bi = tid + FPS_THREADS * (2 * p + 1); }
        }
        buf ^= 1;
    }
    __syncthreads();                                      // sanch complete

    // light tail: publish (q, aidx) packs — 64 threads, 3 LDS + 1 STG.128
    if (tid < ANCHORS) {
        const int aidx = sanch[tid];
        g_qpack[o * ANCHORS + tid] = make_float4(spts[aidx * 3 + 0],
                                                 spts[aidx * 3 + 1],
                                                 spts[aidx * 3 + 2],
                                                 __int_as_float(aidx));
    }
}

// monotonic total-order key for floats (handles tiny negative d2 from cancellation)
__device__ __forceinline__ unsigned fkey(float f) {
    const unsigned u = __float_as_uint(f);
    return (u & 0x80000000u) ? ~u : (u | 0x80000000u);
}
__device__ __forceinline__ float unfkey(unsigned k) {     // exact inverse of fkey
    return __uint_as_float((k & 0x80000000u) ? (k & 0x7FFFFFFFu) : ~k);
}

// ---------------------------------------------------------------------------
// Kernel 2: KNN at anchors + gather + output assembly — R14/R16 champion
// body with ONE delta: the d[16] array is eliminated (regs 96 -> ~80,
// enabling 6 blocks/SM via launch_bounds(128,6); waves 2.77 -> 2.31). The
// accumulation pass RECOMPUTES the distance from the freshly reloaded
// x,y,z with the identical expression — bit-identical d<=T decisions
// (pattern proven in R11, passed 4.68e-8). Pop rounds keep ballot+ffs
// (MANDATORY — ties exist, R3/R12); warp0 merge keeps unfkey T-decode.
// ---------------------------------------------------------------------------
__global__ __launch_bounds__(128, 6) void knn_kernel(const float* __restrict__ pos,
                                                     const float* __restrict__ vel,
                                                     const float* __restrict__ phys,
                                                     const float* __restrict__ refp,
                                                     float* __restrict__ out) {
    __shared__ float cand[4 * KNN];
    __shared__ float sT;
    __shared__ float psum[4][3];

    const int a    = blockIdx.x;                 // global anchor id [0, 2048)
    const int tid  = threadIdx.x;
    const int lane = tid & 31;
    const int wid  = tid >> 5;
    const int obj  = a >> 6;

    const float4 qp = g_qpack[a];                // single 16B load: q + aidx
    const float qx = qp.x, qy = qp.y, qz = qp.z;
    const int aidx = __float_as_int(qp.w);
    const float sqq = qx * qx + qy * qy + qz * qz;

    const float* __restrict__ P = pos + (size_t)obj * N_V * 3;
    const int base = wid << 9;                   // this warp's 512-point chunk

    // ---- distances for my 16 points (v[] only; d recomputed later) ----
    float v[KNN];
#pragma unroll
    for (int k = 0; k < KNN; k++) {
        const int j = base + (k << 5) + lane;
        const float x = P[j * 3 + 0], y = P[j * 3 + 1], z = P[j * 3 + 2];
        float dd = (x * x + y * y + z * z + sqq) - 2.0f * (x * qx + y * qy + z * qz);
        if (j == aidx) dd += 1e10f;              // reference's diagonal exclusion
        v[k] = dd;
    }

    // ---- bitonic sort of the 16 values (ascending), value-only ----
#pragma unroll
    for (int kk = 2; kk <= KNN; kk <<= 1) {
#pragma unroll
        for (int jj = kk >> 1; jj > 0; jj >>= 1) {
#pragma unroll
            for (int i = 0; i < KNN; i++) {
                const int l = i ^ jj;
                if (l > i) {
                    const float va = v[i], vb = v[l];
                    const float lo = fminf(va, vb), hi = fmaxf(va, vb);
                    const bool up = ((i & kk) == 0);
                    v[i] = up ? lo : hi;
                    v[l] = up ? hi : lo;
                }
            }
        }
    }

    // ---- per-warp pop-min extraction: 16 smallest of this warp's 512.
    //      ballot+ffs single winner (MANDATORY — ties exist, R3/R12). ----
    const float FINF = __int_as_float(0x7f800000);
#pragma unroll
    for (int r = 0; r < KNN; r++) {
        const unsigned key = fkey(v[0]);
        const unsigned km  = __reduce_min_sync(FULL, key);
        const unsigned bal = __ballot_sync(FULL, key == km);
        const int win = __ffs(bal) - 1;
        if (lane == win) {
            cand[(wid << 4) + r] = v[0];
#pragma unroll
            for (int t = 0; t < KNN - 1; t++) v[t] = v[t + 1];
            v[KNN - 1] = FINF;
        }
    }
    __syncthreads();

    // ---- warp 0: T = 16th smallest of the 64 candidates. Winner selection
    //      keeps ballot+ffs; T decoded from the last round's km (exact). ----
    if (wid == 0) {
        float c0 = cand[lane * 2], c1 = cand[lane * 2 + 1];
        unsigned kmLast = 0;
#pragma unroll
        for (int r = 0; r < KNN; r++) {
            const unsigned key = fkey(c0);
            const unsigned km  = __reduce_min_sync(FULL, key);
            const unsigned bal = __ballot_sync(FULL, key == km);
            const int win = __ffs(bal) - 1;
            if (lane == win) { c0 = c1; c1 = FINF; }
            kmLast = km;
        }
        if (lane == 0) sT = unfkey(kmLast);
    }
    __syncthreads();
    const float T = sT;

    // ---- accumulate positions with d <= T; distance RECOMPUTED from the
    //      same memory values with the same expression (bit-identical) ----
    float sx = 0.f, sy = 0.f, sz = 0.f;
#pragma unroll
    for (int k = 0; k < KNN; k++) {
        const int j = base + (k << 5) + lane;
        const float x = P[j * 3 + 0], y = P[j * 3 + 1], z = P[j * 3 + 2];
        float dd = (x * x + y * y + z * z + sqq) - 2.0f * (x * qx + y * qy + z * qz);
        if (j == aidx) dd += 1e10f;
        if (dd <= T) { sx += x; sy += y; sz += z; }
    }
#pragma unroll
    for (int off = 16; off; off >>= 1) {
        sx += __shfl_xor_sync(FULL, sx, off);
        sy += __shfl_xor_sync(FULL, sy, off);
        sz += __shfl_xor_sync(FULL, sz, off);
    }
    if (lane == 0) { psum[wid][0] = sx; psum[wid][1] = sy; psum[wid][2] = sz; }
    __syncthreads();

    if (tid == 0) {
        const float nx = psum[0][0] + psum[1][0] + psum[2][0] + psum[3][0];
        const float ny = psum[0][1] + psum[1][1] + psum[2][1] + psum[3][1];
        const float nz = psum[0][2] + psum[1][2] + psum[2][2] + psum[3][2];
        float* __restrict__ o = out + (size_t)a * 12;
        const float inv = 1.0f / 16.0f;
        // anchor_dist: mean(neigh) - p
        o[0] = nx * inv - qx;
        o[1] = ny * inv - qy;
        o[2] = nz * inv - qz;
        // anchor_vel
        const float* __restrict__ V = vel + (size_t)obj * N_V * 3;
        o[3] = V[aidx * 3 + 0];
        o[4] = V[aidx * 3 + 1];
        o[5] = V[aidx * 3 + 2];
        // anchor_rel = pos - ref
        const float* __restrict__ R = refp + (size_t)obj * N_V * 3;
        o[6] = qx - R[aidx * 3 + 0];
        o[7] = qy - R[aidx * 3 + 1];
        o[8] = qz - R[aidx * 3 + 2];
        // physics broadcast
        o[9]  = phys[obj * 3 + 0];
        o[10] = phys[obj * 3 + 1];
        o[11] = phys[obj * 3 + 2];
    }
}

extern "C" void kernel_launch(void* const* d_in, const int* in_sizes, int n_in,
                              void* d_out, int out_size) {
    const float* positions  = (const float*)d_in[0];
    const float* velocities = (const float*)d_in[1];
    const float* physics    = (const float*)d_in[2];
    const float* refpos     = (const float*)d_in[3];
    float* out = (float*)d_out;

    fps_kernel<<<N_OBJS, FPS_THREADS>>>(positions);
    knn_kernel<<<N_OBJS * ANCHORS, 128>>>(positions, velocities, physics, refpos, out);
}